// round 12
// baseline (speedup 1.0000x reference)
#include <cuda_runtime.h>
#include <cuda_fp16.h>
#include <cstdint>
#include <cstddef>

// Problem dims (fixed by the dataset)
#define B_  4
#define S_  2048
#define M_  4096
#define DQ_ 1024
#define DM_ 512
#define BS_ (B_ * S_)   // 8192 total query rows

#define CAPW_ 128        // max selected slots per row (warp attend)
#define MARGIN_ 18.0f    // selection margin in nats below row max (fp16 scores)
#define NTILE_ 32        // score col tiles per row (4096/128)

// ---------------- scratch (static device globals; no allocations) ----------
__device__ __align__(16) __half g_x_h  [(size_t)BS_ * DQ_];
__device__ __align__(16) __half g_x_l  [(size_t)BS_ * DQ_];
__device__ __align__(16) __half g_mem_h[(size_t)B_ * M_ * DM_];
__device__ __align__(16) __half g_wq_h [(size_t)DM_ * DQ_];
__device__ __align__(16) __half g_wq_l [(size_t)DM_ * DQ_];
__device__ __align__(16) __half g_wm_h [(size_t)DQ_ * DM_];
__device__ __align__(16) __half g_wm_l [(size_t)DQ_ * DM_];
__device__ __align__(16) __half g_q_h  [(size_t)BS_ * DM_];
__device__ __align__(16) __half g_q_l  [(size_t)BS_ * DM_];
__device__ __align__(16) __half g_s16  [(size_t)BS_ * M_];      // 64 MB fp16 scores
__device__ __align__(16) float  g_tmax [(size_t)BS_ * NTILE_];  // 1 MB tile maxes
__device__ __align__(16) __half g_att_h[(size_t)BS_ * DM_];

// ---------------- helpers ---------------------------------------------------
__device__ __forceinline__ uint32_t smem_u32(const void* p) {
    return (uint32_t)__cvta_generic_to_shared(p);
}
__device__ __forceinline__ void ldsm4(uint32_t (&r)[4], uint32_t a) {
    asm volatile("ldmatrix.sync.aligned.m8n8.x4.shared.b16 {%0,%1,%2,%3},[%4];\n"
                 : "=r"(r[0]), "=r"(r[1]), "=r"(r[2]), "=r"(r[3]) : "r"(a));
}
__device__ __forceinline__ void mma16816(float (&d)[4], const uint32_t (&a)[4],
                                         const uint32_t* b) {
    asm volatile(
        "mma.sync.aligned.m16n8k16.row.col.f32.f16.f16.f32 "
        "{%0,%1,%2,%3},{%4,%5,%6,%7},{%8,%9},{%0,%1,%2,%3};\n"
        : "+f"(d[0]), "+f"(d[1]), "+f"(d[2]), "+f"(d[3])
        : "r"(a[0]), "r"(a[1]), "r"(a[2]), "r"(a[3]), "r"(b[0]), "r"(b[1]));
}
__device__ __forceinline__ uint32_t h2u(__half2 h) {
    return *reinterpret_cast<uint32_t*>(&h);
}
__device__ __forceinline__ void cpa16(uint32_t s, const void* g) {
    asm volatile("cp.async.cg.shared.global [%0], [%1], 16;\n" :: "r"(s), "l"(g));
}

// ---------------- fused prep: all splits + x copy in one kernel -------------
__global__ void __launch_bounds__(256)
prep_kernel(const float4* __restrict__ x, float4* __restrict__ outx,
            uint2* __restrict__ xh, uint2* __restrict__ xl,
            const float4* __restrict__ mem, uint2* __restrict__ mh,
            const float4* __restrict__ wq, uint2* __restrict__ wqh,
            uint2* __restrict__ wql,
            const float4* __restrict__ wm, uint2* __restrict__ wmh,
            uint2* __restrict__ wml) {
    constexpr int R0 = BS_ * DQ_ / 4;
    constexpr int R1 = B_ * M_ * DM_ / 4;
    constexpr int R2 = DM_ * DQ_ / 4;
    constexpr int R3 = DQ_ * DM_ / 4;
    int i = blockIdx.x * 256 + threadIdx.x;

    if (i < R0) {
        float4 f = x[i];
        outx[i] = f;
        __half hx = __float2half_rn(f.x), hy = __float2half_rn(f.y);
        __half hz = __float2half_rn(f.z), hw = __float2half_rn(f.w);
        uint2 uh, ul;
        uh.x = h2u(__halves2half2(hx, hy));
        uh.y = h2u(__halves2half2(hz, hw));
        ul.x = h2u(__halves2half2(__float2half_rn(f.x - __half2float(hx)),
                                  __float2half_rn(f.y - __half2float(hy))));
        ul.y = h2u(__halves2half2(__float2half_rn(f.z - __half2float(hz)),
                                  __float2half_rn(f.w - __half2float(hw))));
        xh[i] = uh; xl[i] = ul;
    } else if (i < R0 + R1) {
        int j = i - R0;
        float4 f = mem[j];
        uint2 uh;
        uh.x = h2u(__floats2half2_rn(f.x, f.y));
        uh.y = h2u(__floats2half2_rn(f.z, f.w));
        mh[j] = uh;
    } else if (i < R0 + R1 + R2) {
        int j = i - R0 - R1;
        float4 f = wq[j];
        __half hx = __float2half_rn(f.x), hy = __float2half_rn(f.y);
        __half hz = __float2half_rn(f.z), hw = __float2half_rn(f.w);
        uint2 uh, ul;
        uh.x = h2u(__halves2half2(hx, hy));
        uh.y = h2u(__halves2half2(hz, hw));
        ul.x = h2u(__halves2half2(__float2half_rn(f.x - __half2float(hx)),
                                  __float2half_rn(f.y - __half2float(hy))));
        ul.y = h2u(__halves2half2(__float2half_rn(f.z - __half2float(hz)),
                                  __float2half_rn(f.w - __half2float(hw))));
        wqh[j] = uh; wql[j] = ul;
    } else if (i < R0 + R1 + R2 + R3) {
        int j = i - R0 - R1 - R2;
        float4 f = wm[j];
        __half hx = __float2half_rn(f.x), hy = __float2half_rn(f.y);
        __half hz = __float2half_rn(f.z), hw = __float2half_rn(f.w);
        uint2 uh, ul;
        uh.x = h2u(__halves2half2(hx, hy));
        uh.y = h2u(__halves2half2(hz, hw));
        ul.x = h2u(__halves2half2(__float2half_rn(f.x - __half2float(hx)),
                                  __float2half_rn(f.y - __half2float(hy))));
        ul.y = h2u(__halves2half2(__float2half_rn(f.z - __half2float(hz)),
                                  __float2half_rn(f.w - __half2float(hw))));
        wmh[j] = uh; wml[j] = ul;
    }
}

// epilogue writer: 0 = half hi/lo planes, 1 = fp32, 2 = half single plane
template <int OUTM>
__device__ __forceinline__ void write_pair(void* C0, void* C1, size_t off,
                                           float v0, float v1) {
    if constexpr (OUTM == 0) {
        __half h0 = __float2half_rn(v0), h1 = __float2half_rn(v1);
        *reinterpret_cast<__half2*>((__half*)C0 + off) = __halves2half2(h0, h1);
        __half l0 = __float2half_rn(v0 - __half2float(h0));
        __half l1 = __float2half_rn(v1 - __half2float(h1));
        *reinterpret_cast<__half2*>((__half*)C1 + off) = __halves2half2(l0, l1);
    } else if constexpr (OUTM == 1) {
        *reinterpret_cast<float2*>((float*)C0 + off) = make_float2(v0, v1);
    } else {
        *reinterpret_cast<__half2*>((__half*)C0 + off) = __floats2half2_rn(v0, v1);
    }
}

// ---------------- NT GEMM: C = A * B^T (+bias), NT terms --------------------
// cp.async double-buffered, frag-reuse ordering, 2 CTAs/SM target.
template <bool BIAS, int OUTM, int NT, bool TMAX>
__global__ void __launch_bounds__(256, 2)
gemm_nt_c(const __half* __restrict__ Ah, const __half* __restrict__ Al,
          const __half* __restrict__ Bh, const __half* __restrict__ Bl,
          void* __restrict__ C0, void* __restrict__ C1,
          const float* __restrict__ bias,
          int M, int N, int K, size_t aB, size_t bB, size_t cB,
          float* __restrict__ tmaxp) {
    constexpr int BM = 128, BN = 128, BKP = 40;
    constexpr int PL = BM * BKP;  // plane elems per buffer
    extern __shared__ __align__(16) __half sm[];
    __half* AsH = sm;                                        // [2][PL]
    __half* AsL = (NT == 3) ? sm + 2 * PL : sm;
    __half* BsH = sm + (NT == 3 ? 4 : 2) * PL;
    __half* BsL = (NT >= 2) ? BsH + 2 * PL : sm;

    const int tid = threadIdx.x, lane = tid & 31, warp = tid >> 5;
    const int m0 = blockIdx.x * BM, n0 = blockIdx.y * BN, bz = blockIdx.z;
    const __half* Aph = Ah + (size_t)bz * aB + (size_t)m0 * K;
    const __half* Apl = (NT == 3) ? Al + (size_t)bz * aB + (size_t)m0 * K : Aph;
    const __half* Bph = Bh + (size_t)bz * bB + (size_t)n0 * K;
    const __half* Bpl = (NT >= 2) ? Bl + (size_t)bz * bB + (size_t)n0 * K : Bph;

    const int ar0 = tid >> 2, ac = (tid & 3) * 8;
    const uint32_t sAsH = smem_u32(AsH), sAsL = smem_u32(AsL);
    const uint32_t sBsH = smem_u32(BsH), sBsL = smem_u32(BsL);

    float acc[4][4][4];
#pragma unroll
    for (int i = 0; i < 4; i++)
#pragma unroll
        for (int j = 0; j < 4; j++)
#pragma unroll
            for (int k2 = 0; k2 < 4; k2++) acc[i][j][k2] = 0.f;

    const int KT = K / 32;

    auto load_stage = [&](int kt, int buf) {
#pragma unroll
        for (int j = 0; j < 2; j++) {
            const size_t o = (size_t)(ar0 + j * 64) * K + kt * 32 + ac;
            const uint32_t so = (uint32_t)(buf * PL + (ar0 + j * 64) * BKP + ac) * 2;
            cpa16(sAsH + so, Aph + o);
            cpa16(sBsH + so, Bph + o);
            if (NT == 3) cpa16(sAsL + so, Apl + o);
            if (NT >= 2) cpa16(sBsL + so, Bpl + o);
        }
        asm volatile("cp.async.commit_group;\n" ::: "memory");
    };

    load_stage(0, 0);

    const int wm = (warp >> 2) * 64, wn = (warp & 3) * 32;
    const int a_lrow = (lane & 15), a_lcol = (lane >> 4) << 3;
    const int b_lrow = ((lane >> 4) << 3) + (lane & 7);
    const int b_lcol = ((lane >> 3) & 1) << 3;

    int cur = 0;
    for (int kt = 0; kt < KT; kt++) {
        if (kt + 1 < KT) {
            load_stage(kt + 1, cur ^ 1);
            asm volatile("cp.async.wait_group 1;\n" ::: "memory");
        } else {
            asm volatile("cp.async.wait_group 0;\n" ::: "memory");
        }
        __syncthreads();
#pragma unroll
        for (int kk = 0; kk < 2; kk++) {
            const int aoff = cur * PL + (wm + a_lrow) * BKP + kk * 16 + a_lcol;
            const int boff = cur * PL + (wn + b_lrow) * BKP + kk * 16 + b_lcol;
            uint32_t ahf[4][4];
#pragma unroll
            for (int tm = 0; tm < 4; tm++)
                ldsm4(ahf[tm], smem_u32(&AsH[aoff + tm * 16 * BKP]));
            uint32_t bhf[4][2];
#pragma unroll
            for (int t2 = 0; t2 < 2; t2++) {
                uint32_t t[4];
                ldsm4(t, smem_u32(&BsH[boff + t2 * 16 * BKP]));
                bhf[t2 * 2][0] = t[0]; bhf[t2 * 2][1] = t[1];
                bhf[t2 * 2 + 1][0] = t[2]; bhf[t2 * 2 + 1][1] = t[3];
            }
#pragma unroll
            for (int tm = 0; tm < 4; tm++)
#pragma unroll
                for (int tn = 0; tn < 4; tn++) mma16816(acc[tm][tn], ahf[tm], bhf[tn]);

            if (NT == 3) {
                uint32_t alf[4][4];
#pragma unroll
                for (int tm = 0; tm < 4; tm++)
                    ldsm4(alf[tm], smem_u32(&AsL[aoff + tm * 16 * BKP]));
#pragma unroll
                for (int tm = 0; tm < 4; tm++)
#pragma unroll
                    for (int tn = 0; tn < 4; tn++)
                        mma16816(acc[tm][tn], alf[tm], bhf[tn]);
            }
            if (NT >= 2) {
#pragma unroll
                for (int t2 = 0; t2 < 2; t2++) {
                    uint32_t t[4];
                    ldsm4(t, smem_u32(&BsL[boff + t2 * 16 * BKP]));
                    bhf[t2 * 2][0] = t[0]; bhf[t2 * 2][1] = t[1];
                    bhf[t2 * 2 + 1][0] = t[2]; bhf[t2 * 2 + 1][1] = t[3];
                }
#pragma unroll
                for (int tm = 0; tm < 4; tm++)
#pragma unroll
                    for (int tn = 0; tn < 4; tn++)
                        mma16816(acc[tm][tn], ahf[tm], bhf[tn]);
            }
        }
        __syncthreads();
        cur ^= 1;
    }

    const size_t cbase = (size_t)bz * cB;
    const int er = lane >> 2, ec = (lane & 3) * 2;
#pragma unroll
    for (int tm = 0; tm < 4; tm++) {
#pragma unroll
        for (int tn = 0; tn < 4; tn++) {
            int r = m0 + wm + tm * 16 + er;
            int c = n0 + wn + tn * 8 + ec;
            float b0 = 0.f, b1 = 0.f;
            if (BIAS) { b0 = bias[c]; b1 = bias[c + 1]; }
            write_pair<OUTM>(C0, C1, cbase + (size_t)r * N + c,
                             acc[tm][tn][0] + b0, acc[tm][tn][1] + b1);
            write_pair<OUTM>(C0, C1, cbase + (size_t)(r + 8) * N + c,
                             acc[tm][tn][2] + b0, acc[tm][tn][3] + b1);
        }
    }

    if (TMAX) {
        __syncthreads();
        float* sMaxW = reinterpret_cast<float*>(sm);  // [4][128]
#pragma unroll
        for (int tm = 0; tm < 4; tm++) {
            float m0v = -1e30f, m1v = -1e30f;
#pragma unroll
            for (int tn = 0; tn < 4; tn++) {
                m0v = fmaxf(m0v, fmaxf(acc[tm][tn][0], acc[tm][tn][1]));
                m1v = fmaxf(m1v, fmaxf(acc[tm][tn][2], acc[tm][tn][3]));
            }
            m0v = fmaxf(m0v, __shfl_xor_sync(0xffffffffu, m0v, 1));
            m0v = fmaxf(m0v, __shfl_xor_sync(0xffffffffu, m0v, 2));
            m1v = fmaxf(m1v, __shfl_xor_sync(0xffffffffu, m1v, 1));
            m1v = fmaxf(m1v, __shfl_xor_sync(0xffffffffu, m1v, 2));
            if ((lane & 3) == 0) {
                sMaxW[(warp & 3) * 128 + wm + tm * 16 + er] = m0v;
                sMaxW[(warp & 3) * 128 + wm + tm * 16 + er + 8] = m1v;
            }
        }
        __syncthreads();
        if (tid < 128) {
            float v = fmaxf(fmaxf(sMaxW[tid], sMaxW[128 + tid]),
                            fmaxf(sMaxW[256 + tid], sMaxW[384 + tid]));
            tmaxp[(size_t)(bz * M + m0 + tid) * gridDim.y + blockIdx.y] = v;
        }
    }
}

// ---- warp-per-row attend: single-pass online softmax, 4-way unrolled -------
// 4 rows per 128-thread block. Lane owns dims [lane*16, lane*16+16).
__global__ void __launch_bounds__(128)
attend_kernel(const __half* __restrict__ s16, const float* __restrict__ tmax,
              const __half* __restrict__ qh, const __half* __restrict__ ql,
              const float* __restrict__ mem, __half* __restrict__ ah) {
    const int wid = threadIdx.x >> 5, lane = threadIdx.x & 31;
    const int row = blockIdx.x * 4 + wid;
    const int b = row >> 11;

    __shared__ int sidx[4][CAPW_];
    __shared__ int scnt[4];
    if (lane == 0) scnt[wid] = 0;
    __syncwarp();

    // tile maxes -> row max (lane t holds tile t)
    const float tv = tmax[(size_t)row * NTILE_ + lane];
    float mm = tv;
#pragma unroll
    for (int s = 16; s; s >>= 1) mm = fmaxf(mm, __shfl_xor_sync(0xffffffffu, mm, s));
    const float thr = mm - MARGIN_;
    const unsigned tmask = __ballot_sync(0xffffffffu, tv >= thr);

    // exact q: lane's 16 dims (16 halves = 32 B = two uint4 per plane)
    float qv[16];
    {
        const uint4* ph = reinterpret_cast<const uint4*>(qh + (size_t)row * DM_ + lane * 16);
        const uint4* pl = reinterpret_cast<const uint4*>(ql + (size_t)row * DM_ + lane * 16);
        uint4 uh[2] = {ph[0], ph[1]};
        uint4 ul[2] = {pl[0], pl[1]};
        const __half2* hh = reinterpret_cast<const __half2*>(uh);
        const __half2* ll = reinterpret_cast<const __half2*>(ul);
#pragma unroll
        for (int j = 0; j < 8; j++) {
            float2 a = __half22float2(hh[j]);
            float2 c = __half22float2(ll[j]);
            qv[2 * j] = a.x + c.x;
            qv[2 * j + 1] = a.y + c.y;
        }
    }

    // scan qualifying tiles: lane reads 4 contiguous fp16 scores per tile
    const __half* srow = s16 + (size_t)row * M_;
    unsigned rem = tmask;
    while (rem) {
        const int t = __ffs(rem) - 1;
        rem &= rem - 1;
        const uint2 u = *reinterpret_cast<const uint2*>(srow + t * 128 + lane * 4);
        const __half2 h0 = *reinterpret_cast<const __half2*>(&u.x);
        const __half2 h1 = *reinterpret_cast<const __half2*>(&u.y);
        const float2 f0 = __half22float2(h0), f1 = __half22float2(h1);
        const float vv[4] = {f0.x, f0.y, f1.x, f1.y};
#pragma unroll
        for (int c = 0; c < 4; c++) {
            if (vv[c] >= thr) {
                int pos = atomicAdd(&scnt[wid], 1);
                if (pos < CAPW_) sidx[wid][pos] = t * 128 + lane * 4 + c;
            }
        }
    }
    __syncwarp();
    const int n = scnt[wid] < CAPW_ ? scnt[wid] : CAPW_;

    // single pass: exact rescore + online softmax + PV, 4 candidates/round
    const float* mb = mem + (size_t)b * M_ * DM_;
    const float L2E = 1.4426950408889634f;
    float mrun = -1e30f, srun = 0.f;
    float facc[16];
#pragma unroll
    for (int c = 0; c < 16; c++) facc[c] = 0.f;

    for (int i = 0; i < n; i += 4) {
        const int nleft = n - i;
        const int j1 = nleft > 1 ? i + 1 : i;
        const int j2 = nleft > 2 ? i + 2 : i;
        const int j3 = nleft > 3 ? i + 3 : i;
        const float* mr0 = mb + (size_t)sidx[wid][i]  * DM_ + lane * 16;
        const float* mr1 = mb + (size_t)sidx[wid][j1] * DM_ + lane * 16;
        const float* mr2 = mb + (size_t)sidx[wid][j2] * DM_ + lane * 16;
        const float* mr3 = mb + (size_t)sidx[wid][j3] * DM_ + lane * 16;
        // load 4 rows (16 independent float4 loads -> high MLP)
        float4 r0[4], r1[4], r2[4], r3[4];
#pragma unroll
        for (int c = 0; c < 4; c++) r0[c] = *reinterpret_cast<const float4*>(mr0 + c * 4);
#pragma unroll
        for (int c = 0; c < 4; c++) r1[c] = *reinterpret_cast<const float4*>(mr1 + c * 4);
#pragma unroll
        for (int c = 0; c < 4; c++) r2[c] = *reinterpret_cast<const float4*>(mr2 + c * 4);
#pragma unroll
        for (int c = 0; c < 4; c++) r3[c] = *reinterpret_cast<const float4*>(mr3 + c * 4);
        // four independent dot-reduction chains
        float d0 = 0.f, d1 = 0.f, d2 = 0.f, d3 = 0.f;
#pragma unroll
        for (int c = 0; c < 4; c++) {
            d0 += qv[c * 4] * r0[c].x + qv[c * 4 + 1] * r0[c].y +
                  qv[c * 4 + 2] * r0[c].z + qv[c * 4 + 3] * r0[c].w;
            d1 += qv[c * 4] * r1[c].x + qv[c * 4 + 1] * r1[c].y +
                  qv[c * 4 + 2] * r1[c].z + qv[c * 4 + 3] * r1[c].w;
            d2 += qv[c * 4] * r2[c].x + qv[c * 4 + 1] * r2[c].y +
                  qv[c * 4 + 2] * r2[c].z + qv[c * 4 + 3] * r2[c].w;
            d3 += qv[c * 4] * r3[c].x + qv[c * 4 + 1] * r3[c].y +
                  qv[c * 4 + 2] * r3[c].z + qv[c * 4 + 3] * r3[c].w;
        }
#pragma unroll
        for (int s = 16; s; s >>= 1) {
            d0 += __shfl_xor_sync(0xffffffffu, d0, s);
            d1 += __shfl_xor_sync(0xffffffffu, d1, s);
            d2 += __shfl_xor_sync(0xffffffffu, d2, s);
            d3 += __shfl_xor_sync(0xffffffffu, d3, s);
        }
        // mask clamped duplicates out of BOTH the max and the sum
        const float md1 = nleft > 1 ? d1 : -1e30f;
        const float md2 = nleft > 2 ? d2 : -1e30f;
        const float md3 = nleft > 3 ? d3 : -1e30f;
        const float mnew =
            fmaxf(mrun, fmaxf(fmaxf(d0, md1), fmaxf(md2, md3)));
        const float scale = exp2f((mrun - mnew) * L2E);
        const float e0 = exp2f((d0 - mnew) * L2E);
        const float e1 = nleft > 1 ? exp2f((d1 - mnew) * L2E) : 0.f;
        const float e2 = nleft > 2 ? exp2f((d2 - mnew) * L2E) : 0.f;
        const float e3 = nleft > 3 ? exp2f((d3 - mnew) * L2E) : 0.f;
        srun = srun * scale + e0 + e1 + e2 + e3;
#pragma unroll
        for (int c = 0; c < 4; c++) {
            facc[c * 4]     = facc[c * 4]     * scale + e0 * r0[c].x + e1 * r1[c].x +
                              e2 * r2[c].x + e3 * r3[c].x;
            facc[c * 4 + 1] = facc[c * 4 + 1] * scale + e0 * r0[c].y + e1 * r1[c].y +
                              e2 * r2[c].y + e3 * r3[c].y;
            facc[c * 4 + 2] = facc[c * 4 + 2] * scale + e0 * r0[c].z + e1 * r1[c].z +
                              e2 * r2[c].z + e3 * r3[c].z;
            facc[c * 4 + 3] = facc[c * 4 + 3] * scale + e0 * r0[c].w + e1 * r1[c].w +
                              e2 * r2[c].w + e3 * r3[c].w;
        }
        mrun = mnew;
    }
    const float inv = 1.f / srun;

    uint4 o[2];
    uint32_t* op = reinterpret_cast<uint32_t*>(o);
#pragma unroll
    for (int j = 0; j < 8; j++)
        op[j] = h2u(__floats2half2_rn(facc[2 * j] * inv, facc[2 * j + 1] * inv));
    uint4* dst = reinterpret_cast<uint4*>(ah + (size_t)row * DM_ + lane * 16);
    dst[0] = o[0];
    dst[1] = o[1];
}

// ---------------- launch -----------------------------------------------------
extern "C" void kernel_launch(void* const* d_in, const int* in_sizes, int n_in,
                              void* d_out, int out_size) {
    const float* x   = (const float*)d_in[0];
    const float* mem = (const float*)d_in[1];
    const float* Wq  = (const float*)d_in[2];
    const float* bq  = (const float*)d_in[3];
    const float* Wm  = (const float*)d_in[4];
    const float* bm  = (const float*)d_in[5];
    float* out = (float*)d_out;

    __half *xh, *xl, *mh, *wqh, *wql, *wmh, *wml, *qh, *ql, *s16, *ah;
    float *tmx;
    cudaGetSymbolAddress((void**)&xh,  g_x_h);   cudaGetSymbolAddress((void**)&xl,  g_x_l);
    cudaGetSymbolAddress((void**)&mh,  g_mem_h);
    cudaGetSymbolAddress((void**)&wqh, g_wq_h);  cudaGetSymbolAddress((void**)&wql, g_wq_l);
    cudaGetSymbolAddress((void**)&wmh, g_wm_h);  cudaGetSymbolAddress((void**)&wml, g_wm_l);
    cudaGetSymbolAddress((void**)&qh,  g_q_h);   cudaGetSymbolAddress((void**)&ql,  g_q_l);
    cudaGetSymbolAddress((void**)&s16, g_s16);   cudaGetSymbolAddress((void**)&tmx, g_tmax);
    cudaGetSymbolAddress((void**)&ah,  g_att_h);

    constexpr int SM3 = 8 * 128 * 40 * 2;  // 81920 B (3-term)
    constexpr int SM2 = 6 * 128 * 40 * 2;  // 61440 B (2-term)
    constexpr int SM1 = 4 * 128 * 40 * 2;  // 40960 B (1-term)
    cudaFuncSetAttribute(gemm_nt_c<true, 0, 3, false>,
                         cudaFuncAttributeMaxDynamicSharedMemorySize, SM3);
    cudaFuncSetAttribute(gemm_nt_c<false, 2, 1, true>,
                         cudaFuncAttributeMaxDynamicSharedMemorySize, SM1);
    cudaFuncSetAttribute(gemm_nt_c<true, 1, 2, false>,
                         cudaFuncAttributeMaxDynamicSharedMemorySize, SM2);

    // 0) fused prep: x copy+split, mem hi-split, Wq/Wm splits (one kernel)
    constexpr int PREP_BLOCKS =
        (BS_ * DQ_ / 4 + B_ * M_ * DM_ / 4 + DM_ * DQ_ / 4 + DQ_ * DM_ / 4) / 256;
    prep_kernel<<<PREP_BLOCKS, 256>>>(
        (const float4*)x, (float4*)out, (uint2*)xh, (uint2*)xl,
        (const float4*)mem, (uint2*)mh,
        (const float4*)Wq, (uint2*)wqh, (uint2*)wql,
        (const float4*)Wm, (uint2*)wmh, (uint2*)wml);

    // 1) query = x @ Wq^T + bq  (3-term exact) -> hi/lo planes [8192, 512]
    gemm_nt_c<true, 0, 3, false><<<dim3(64, 4, 1), 256, SM3>>>(
        xh, xl, wqh, wql, qh, ql, bq, BS_, DM_, DQ_, 0, 0, 0, nullptr);

    // 2) scores(approx) = q_h @ mem_h^T (1-term fp16) + per-row tile maxes
    gemm_nt_c<false, 2, 1, true><<<dim3(16, 32, 4), 256, SM1>>>(
        qh, nullptr, mh, nullptr, s16, nullptr, nullptr, S_, M_, DM_,
        (size_t)S_ * DM_, (size_t)M_ * DM_, (size_t)S_ * M_, tmx);

    // 3) warp-per-row attend: single-pass online softmax + exact PV (4-way)
    attend_kernel<<<BS_ / 4, 128>>>(s16, tmx, qh, ql, mem, ah);

    // 4) transformed = attended_h @ (Wm_h+Wm_l)^T + bm (2-term) -> out tail
    gemm_nt_c<true, 1, 2, false><<<dim3(64, 8, 1), 256, SM2>>>(
        ah, nullptr, wmh, wml, out + (size_t)BS_ * DQ_, nullptr, bm,
        BS_, DQ_, DM_, 0, 0, 0, nullptr);
}

// round 14
// speedup vs baseline: 1.0709x; 1.0709x over previous
#include <cuda_runtime.h>
#include <cuda_fp16.h>
#include <cstdint>
#include <cstddef>

// Problem dims (fixed by the dataset)
#define B_  4
#define S_  2048
#define M_  4096
#define DQ_ 1024
#define DM_ 512
#define BS_ (B_ * S_)   // 8192 total query rows

#define CAPW_ 128        // max selected slots per row (warp attend)
#define MARGIN_ 18.0f    // selection margin in nats below row max (fp16 scores)
#define NTILE_ 32        // score col tiles per row (4096/128)

// ---------------- scratch (static device globals; no allocations) ----------
__device__ __align__(16) __half g_x_h  [(size_t)BS_ * DQ_];
__device__ __align__(16) __half g_x_l  [(size_t)BS_ * DQ_];
__device__ __align__(16) __half g_mem_h[(size_t)B_ * M_ * DM_];
__device__ __align__(16) __half g_wq_h [(size_t)DM_ * DQ_];
__device__ __align__(16) __half g_wq_l [(size_t)DM_ * DQ_];
__device__ __align__(16) __half g_wm_h [(size_t)DQ_ * DM_];
__device__ __align__(16) __half g_q_h  [(size_t)BS_ * DM_];
__device__ __align__(16) __half g_q_l  [(size_t)BS_ * DM_];
__device__ __align__(16) __half g_s16  [(size_t)BS_ * M_];      // 64 MB fp16 scores
__device__ __align__(16) float  g_tmax [(size_t)BS_ * NTILE_];  // 1 MB tile maxes
__device__ __align__(16) __half g_att_h[(size_t)BS_ * DM_];

// ---------------- helpers ---------------------------------------------------
__device__ __forceinline__ uint32_t smem_u32(const void* p) {
    return (uint32_t)__cvta_generic_to_shared(p);
}
__device__ __forceinline__ void ldsm4(uint32_t (&r)[4], uint32_t a) {
    asm volatile("ldmatrix.sync.aligned.m8n8.x4.shared.b16 {%0,%1,%2,%3},[%4];\n"
                 : "=r"(r[0]), "=r"(r[1]), "=r"(r[2]), "=r"(r[3]) : "r"(a));
}
__device__ __forceinline__ void mma16816(float (&d)[4], const uint32_t (&a)[4],
                                         const uint32_t* b) {
    asm volatile(
        "mma.sync.aligned.m16n8k16.row.col.f32.f16.f16.f32 "
        "{%0,%1,%2,%3},{%4,%5,%6,%7},{%8,%9},{%0,%1,%2,%3};\n"
        : "+f"(d[0]), "+f"(d[1]), "+f"(d[2]), "+f"(d[3])
        : "r"(a[0]), "r"(a[1]), "r"(a[2]), "r"(a[3]), "r"(b[0]), "r"(b[1]));
}
__device__ __forceinline__ uint32_t h2u(__half2 h) {
    return *reinterpret_cast<uint32_t*>(&h);
}
__device__ __forceinline__ void cpa16(uint32_t s, const void* g) {
    asm volatile("cp.async.cg.shared.global [%0], [%1], 16;\n" :: "r"(s), "l"(g));
}

// ---------------- fused prep: needed splits + x copy in one kernel ----------
// regions (float4 units): [0,R0) x copy + hi/lo split, [R0,R0+R1) mem hi-split,
// [.., +R2) Wq hi/lo split, [.., +R3) Wm hi-split.
__global__ void __launch_bounds__(256)
prep_kernel(const float4* __restrict__ x, float4* __restrict__ outx,
            uint2* __restrict__ xh, uint2* __restrict__ xl,
            const float4* __restrict__ mem, uint2* __restrict__ mh,
            const float4* __restrict__ wq, uint2* __restrict__ wqh,
            uint2* __restrict__ wql,
            const float4* __restrict__ wm, uint2* __restrict__ wmh) {
    constexpr int R0 = BS_ * DQ_ / 4;
    constexpr int R1 = B_ * M_ * DM_ / 4;
    constexpr int R2 = DM_ * DQ_ / 4;
    constexpr int R3 = DQ_ * DM_ / 4;
    int i = blockIdx.x * 256 + threadIdx.x;

    if (i < R0) {
        float4 f = x[i];
        outx[i] = f;
        __half hx = __float2half_rn(f.x), hy = __float2half_rn(f.y);
        __half hz = __float2half_rn(f.z), hw = __float2half_rn(f.w);
        uint2 uh, ul;
        uh.x = h2u(__halves2half2(hx, hy));
        uh.y = h2u(__halves2half2(hz, hw));
        ul.x = h2u(__halves2half2(__float2half_rn(f.x - __half2float(hx)),
                                  __float2half_rn(f.y - __half2float(hy))));
        ul.y = h2u(__halves2half2(__float2half_rn(f.z - __half2float(hz)),
                                  __float2half_rn(f.w - __half2float(hw))));
        xh[i] = uh; xl[i] = ul;
    } else if (i < R0 + R1) {
        int j = i - R0;
        float4 f = mem[j];
        uint2 uh;
        uh.x = h2u(__floats2half2_rn(f.x, f.y));
        uh.y = h2u(__floats2half2_rn(f.z, f.w));
        mh[j] = uh;
    } else if (i < R0 + R1 + R2) {
        int j = i - R0 - R1;
        float4 f = wq[j];
        __half hx = __float2half_rn(f.x), hy = __float2half_rn(f.y);
        __half hz = __float2half_rn(f.z), hw = __float2half_rn(f.w);
        uint2 uh, ul;
        uh.x = h2u(__halves2half2(hx, hy));
        uh.y = h2u(__halves2half2(hz, hw));
        ul.x = h2u(__halves2half2(__float2half_rn(f.x - __half2float(hx)),
                                  __float2half_rn(f.y - __half2float(hy))));
        ul.y = h2u(__halves2half2(__float2half_rn(f.z - __half2float(hz)),
                                  __float2half_rn(f.w - __half2float(hw))));
        wqh[j] = uh; wql[j] = ul;
    } else if (i < R0 + R1 + R2 + R3) {
        int j = i - R0 - R1 - R2;
        float4 f = wm[j];
        uint2 uh;
        uh.x = h2u(__floats2half2_rn(f.x, f.y));
        uh.y = h2u(__floats2half2_rn(f.z, f.w));
        wmh[j] = uh;
    }
}

// epilogue writer: 0 = half hi/lo planes, 1 = fp32, 2 = half single plane
template <int OUTM>
__device__ __forceinline__ void write_pair(void* C0, void* C1, size_t off,
                                           float v0, float v1) {
    if constexpr (OUTM == 0) {
        __half h0 = __float2half_rn(v0), h1 = __float2half_rn(v1);
        *reinterpret_cast<__half2*>((__half*)C0 + off) = __halves2half2(h0, h1);
        __half l0 = __float2half_rn(v0 - __half2float(h0));
        __half l1 = __float2half_rn(v1 - __half2float(h1));
        *reinterpret_cast<__half2*>((__half*)C1 + off) = __halves2half2(l0, l1);
    } else if constexpr (OUTM == 1) {
        *reinterpret_cast<float2*>((float*)C0 + off) = make_float2(v0, v1);
    } else {
        *reinterpret_cast<__half2*>((__half*)C0 + off) = __floats2half2_rn(v0, v1);
    }
}

// ---------------- NT GEMM: C = A * B^T (+bias), NT terms --------------------
// cp.async double-buffered, frag-reuse ordering, 2 CTAs/SM target.
// NT==3: Ah*Bh + Al*Bh + Ah*Bl.  NT==2: Ah*Bh + Ah*Bl.  NT==1: Ah*Bh.
template <bool BIAS, int OUTM, int NT, bool TMAX>
__global__ void __launch_bounds__(256, 2)
gemm_nt_c(const __half* __restrict__ Ah, const __half* __restrict__ Al,
          const __half* __restrict__ Bh, const __half* __restrict__ Bl,
          void* __restrict__ C0, void* __restrict__ C1,
          const float* __restrict__ bias,
          int M, int N, int K, size_t aB, size_t bB, size_t cB,
          float* __restrict__ tmaxp) {
    constexpr int BM = 128, BN = 128, BKP = 40;
    constexpr int PL = BM * BKP;  // plane elems per buffer
    extern __shared__ __align__(16) __half sm[];
    __half* AsH = sm;                                        // [2][PL]
    __half* AsL = (NT == 3) ? sm + 2 * PL : sm;
    __half* BsH = sm + (NT == 3 ? 4 : 2) * PL;
    __half* BsL = (NT >= 2) ? BsH + 2 * PL : sm;

    const int tid = threadIdx.x, lane = tid & 31, warp = tid >> 5;
    const int m0 = blockIdx.x * BM, n0 = blockIdx.y * BN, bz = blockIdx.z;
    const __half* Aph = Ah + (size_t)bz * aB + (size_t)m0 * K;
    const __half* Apl = (NT == 3) ? Al + (size_t)bz * aB + (size_t)m0 * K : Aph;
    const __half* Bph = Bh + (size_t)bz * bB + (size_t)n0 * K;
    const __half* Bpl = (NT >= 2) ? Bl + (size_t)bz * bB + (size_t)n0 * K : Bph;

    const int ar0 = tid >> 2, ac = (tid & 3) * 8;
    const uint32_t sAsH = smem_u32(AsH), sAsL = smem_u32(AsL);
    const uint32_t sBsH = smem_u32(BsH), sBsL = smem_u32(BsL);

    float acc[4][4][4];
#pragma unroll
    for (int i = 0; i < 4; i++)
#pragma unroll
        for (int j = 0; j < 4; j++)
#pragma unroll
            for (int k2 = 0; k2 < 4; k2++) acc[i][j][k2] = 0.f;

    const int KT = K / 32;

    auto load_stage = [&](int kt, int buf) {
#pragma unroll
        for (int j = 0; j < 2; j++) {
            const size_t o = (size_t)(ar0 + j * 64) * K + kt * 32 + ac;
            const uint32_t so = (uint32_t)(buf * PL + (ar0 + j * 64) * BKP + ac) * 2;
            cpa16(sAsH + so, Aph + o);
            cpa16(sBsH + so, Bph + o);
            if (NT == 3) cpa16(sAsL + so, Apl + o);
            if (NT >= 2) cpa16(sBsL + so, Bpl + o);
        }
        asm volatile("cp.async.commit_group;\n" ::: "memory");
    };

    load_stage(0, 0);

    const int wm = (warp >> 2) * 64, wn = (warp & 3) * 32;
    const int a_lrow = (lane & 15), a_lcol = (lane >> 4) << 3;
    const int b_lrow = ((lane >> 4) << 3) + (lane & 7);
    const int b_lcol = ((lane >> 3) & 1) << 3;

    int cur = 0;
    for (int kt = 0; kt < KT; kt++) {
        if (kt + 1 < KT) {
            load_stage(kt + 1, cur ^ 1);
            asm volatile("cp.async.wait_group 1;\n" ::: "memory");
        } else {
            asm volatile("cp.async.wait_group 0;\n" ::: "memory");
        }
        __syncthreads();
#pragma unroll
        for (int kk = 0; kk < 2; kk++) {
            const int aoff = cur * PL + (wm + a_lrow) * BKP + kk * 16 + a_lcol;
            const int boff = cur * PL + (wn + b_lrow) * BKP + kk * 16 + b_lcol;
            uint32_t ahf[4][4];
#pragma unroll
            for (int tm = 0; tm < 4; tm++)
                ldsm4(ahf[tm], smem_u32(&AsH[aoff + tm * 16 * BKP]));
            uint32_t bhf[4][2];
#pragma unroll
            for (int t2 = 0; t2 < 2; t2++) {
                uint32_t t[4];
                ldsm4(t, smem_u32(&BsH[boff + t2 * 16 * BKP]));
                bhf[t2 * 2][0] = t[0]; bhf[t2 * 2][1] = t[1];
                bhf[t2 * 2 + 1][0] = t[2]; bhf[t2 * 2 + 1][1] = t[3];
            }
#pragma unroll
            for (int tm = 0; tm < 4; tm++)
#pragma unroll
                for (int tn = 0; tn < 4; tn++) mma16816(acc[tm][tn], ahf[tm], bhf[tn]);

            if (NT == 3) {
                uint32_t alf[4][4];
#pragma unroll
                for (int tm = 0; tm < 4; tm++)
                    ldsm4(alf[tm], smem_u32(&AsL[aoff + tm * 16 * BKP]));
#pragma unroll
                for (int tm = 0; tm < 4; tm++)
#pragma unroll
                    for (int tn = 0; tn < 4; tn++)
                        mma16816(acc[tm][tn], alf[tm], bhf[tn]);
            }
            if (NT >= 2) {
#pragma unroll
                for (int t2 = 0; t2 < 2; t2++) {
                    uint32_t t[4];
                    ldsm4(t, smem_u32(&BsL[boff + t2 * 16 * BKP]));
                    bhf[t2 * 2][0] = t[0]; bhf[t2 * 2][1] = t[1];
                    bhf[t2 * 2 + 1][0] = t[2]; bhf[t2 * 2 + 1][1] = t[3];
                }
#pragma unroll
                for (int tm = 0; tm < 4; tm++)
#pragma unroll
                    for (int tn = 0; tn < 4; tn++)
                        mma16816(acc[tm][tn], ahf[tm], bhf[tn]);
            }
        }
        __syncthreads();
        cur ^= 1;
    }

    const size_t cbase = (size_t)bz * cB;
    const int er = lane >> 2, ec = (lane & 3) * 2;
#pragma unroll
    for (int tm = 0; tm < 4; tm++) {
#pragma unroll
        for (int tn = 0; tn < 4; tn++) {
            int r = m0 + wm + tm * 16 + er;
            int c = n0 + wn + tn * 8 + ec;
            float b0 = 0.f, b1 = 0.f;
            if (BIAS) { b0 = bias[c]; b1 = bias[c + 1]; }
            write_pair<OUTM>(C0, C1, cbase + (size_t)r * N + c,
                             acc[tm][tn][0] + b0, acc[tm][tn][1] + b1);
            write_pair<OUTM>(C0, C1, cbase + (size_t)(r + 8) * N + c,
                             acc[tm][tn][2] + b0, acc[tm][tn][3] + b1);
        }
    }

    if (TMAX) {
        __syncthreads();
        float* sMaxW = reinterpret_cast<float*>(sm);  // [4][128]
#pragma unroll
        for (int tm = 0; tm < 4; tm++) {
            float m0v = -1e30f, m1v = -1e30f;
#pragma unroll
            for (int tn = 0; tn < 4; tn++) {
                m0v = fmaxf(m0v, fmaxf(acc[tm][tn][0], acc[tm][tn][1]));
                m1v = fmaxf(m1v, fmaxf(acc[tm][tn][2], acc[tm][tn][3]));
            }
            m0v = fmaxf(m0v, __shfl_xor_sync(0xffffffffu, m0v, 1));
            m0v = fmaxf(m0v, __shfl_xor_sync(0xffffffffu, m0v, 2));
            m1v = fmaxf(m1v, __shfl_xor_sync(0xffffffffu, m1v, 1));
            m1v = fmaxf(m1v, __shfl_xor_sync(0xffffffffu, m1v, 2));
            if ((lane & 3) == 0) {
                sMaxW[(warp & 3) * 128 + wm + tm * 16 + er] = m0v;
                sMaxW[(warp & 3) * 128 + wm + tm * 16 + er + 8] = m1v;
            }
        }
        __syncthreads();
        if (tid < 128) {
            float v = fmaxf(fmaxf(sMaxW[tid], sMaxW[128 + tid]),
                            fmaxf(sMaxW[256 + tid], sMaxW[384 + tid]));
            tmaxp[(size_t)(bz * M + m0 + tid) * gridDim.y + blockIdx.y] = v;
        }
    }
}

// ---- warp-per-row attend: single-pass online softmax, 2-way unrolled -------
// 4 rows per 128-thread block. Lane owns dims [lane*16, lane*16+16).
__global__ void __launch_bounds__(128)
attend_kernel(const __half* __restrict__ s16, const float* __restrict__ tmax,
              const __half* __restrict__ qh, const __half* __restrict__ ql,
              const float* __restrict__ mem, __half* __restrict__ ah) {
    const int wid = threadIdx.x >> 5, lane = threadIdx.x & 31;
    const int row = blockIdx.x * 4 + wid;
    const int b = row >> 11;

    __shared__ int sidx[4][CAPW_];
    __shared__ int scnt[4];
    if (lane == 0) scnt[wid] = 0;
    __syncwarp();

    // tile maxes -> row max (lane t holds tile t)
    const float tv = tmax[(size_t)row * NTILE_ + lane];
    float mm = tv;
#pragma unroll
    for (int s = 16; s; s >>= 1) mm = fmaxf(mm, __shfl_xor_sync(0xffffffffu, mm, s));
    const float thr = mm - MARGIN_;
    const unsigned tmask = __ballot_sync(0xffffffffu, tv >= thr);

    // exact q: lane's 16 dims (16 halves = 32 B = two uint4 per plane)
    float qv[16];
    {
        const uint4* ph = reinterpret_cast<const uint4*>(qh + (size_t)row * DM_ + lane * 16);
        const uint4* pl = reinterpret_cast<const uint4*>(ql + (size_t)row * DM_ + lane * 16);
        uint4 uh[2] = {ph[0], ph[1]};
        uint4 ul[2] = {pl[0], pl[1]};
        const __half2* hh = reinterpret_cast<const __half2*>(uh);
        const __half2* ll = reinterpret_cast<const __half2*>(ul);
#pragma unroll
        for (int j = 0; j < 8; j++) {
            float2 a = __half22float2(hh[j]);
            float2 c = __half22float2(ll[j]);
            qv[2 * j] = a.x + c.x;
            qv[2 * j + 1] = a.y + c.y;
        }
    }

    // scan qualifying tiles: lane reads 4 contiguous fp16 scores per tile
    const __half* srow = s16 + (size_t)row * M_;
    unsigned rem = tmask;
    while (rem) {
        const int t = __ffs(rem) - 1;
        rem &= rem - 1;
        const uint2 u = *reinterpret_cast<const uint2*>(srow + t * 128 + lane * 4);
        const __half2 h0 = *reinterpret_cast<const __half2*>(&u.x);
        const __half2 h1 = *reinterpret_cast<const __half2*>(&u.y);
        const float2 f0 = __half22float2(h0), f1 = __half22float2(h1);
        const float vv[4] = {f0.x, f0.y, f1.x, f1.y};
#pragma unroll
        for (int c = 0; c < 4; c++) {
            if (vv[c] >= thr) {
                int pos = atomicAdd(&scnt[wid], 1);
                if (pos < CAPW_) sidx[wid][pos] = t * 128 + lane * 4 + c;
            }
        }
    }
    __syncwarp();
    const int n = scnt[wid] < CAPW_ ? scnt[wid] : CAPW_;

    // single pass: exact rescore + online softmax + PV, 2 candidates/round
    const float* mb = mem + (size_t)b * M_ * DM_;
    const float L2E = 1.4426950408889634f;
    float mrun = -1e30f, srun = 0.f;
    float facc[16];
#pragma unroll
    for (int c = 0; c < 16; c++) facc[c] = 0.f;

    for (int i = 0; i < n; i += 2) {
        const bool two = (i + 1 < n);
        const float* mr0 = mb + (size_t)sidx[wid][i] * DM_ + lane * 16;
        const float* mr1 = mb + (size_t)sidx[wid][two ? i + 1 : i] * DM_ + lane * 16;
        // load both rows (8 independent float4 loads -> high MLP)
        float4 r0[4], r1[4];
#pragma unroll
        for (int c = 0; c < 4; c++) r0[c] = *reinterpret_cast<const float4*>(mr0 + c * 4);
#pragma unroll
        for (int c = 0; c < 4; c++) r1[c] = *reinterpret_cast<const float4*>(mr1 + c * 4);
        // two independent dot-reduction chains
        float d0 = 0.f, d1 = 0.f;
#pragma unroll
        for (int c = 0; c < 4; c++) {
            d0 += qv[c * 4] * r0[c].x + qv[c * 4 + 1] * r0[c].y +
                  qv[c * 4 + 2] * r0[c].z + qv[c * 4 + 3] * r0[c].w;
            d1 += qv[c * 4] * r1[c].x + qv[c * 4 + 1] * r1[c].y +
                  qv[c * 4 + 2] * r1[c].z + qv[c * 4 + 3] * r1[c].w;
        }
#pragma unroll
        for (int s = 16; s; s >>= 1) {
            d0 += __shfl_xor_sync(0xffffffffu, d0, s);
            d1 += __shfl_xor_sync(0xffffffffu, d1, s);
        }
        if (!two) d1 = -1e30f;
        // online softmax merge
        const float mnew = fmaxf(mrun, fmaxf(d0, d1));
        const float scale = exp2f((mrun - mnew) * L2E);
        const float e0 = exp2f((d0 - mnew) * L2E);
        const float e1 = two ? exp2f((d1 - mnew) * L2E) : 0.f;
        srun = srun * scale + e0 + e1;
#pragma unroll
        for (int c = 0; c < 4; c++) {
            facc[c * 4]     = facc[c * 4]     * scale + e0 * r0[c].x + e1 * r1[c].x;
            facc[c * 4 + 1] = facc[c * 4 + 1] * scale + e0 * r0[c].y + e1 * r1[c].y;
            facc[c * 4 + 2] = facc[c * 4 + 2] * scale + e0 * r0[c].z + e1 * r1[c].z;
            facc[c * 4 + 3] = facc[c * 4 + 3] * scale + e0 * r0[c].w + e1 * r1[c].w;
        }
        mrun = mnew;
    }
    const float inv = 1.f / srun;

    uint4 o[2];
    uint32_t* op = reinterpret_cast<uint32_t*>(o);
#pragma unroll
    for (int j = 0; j < 8; j++)
        op[j] = h2u(__floats2half2_rn(facc[2 * j] * inv, facc[2 * j + 1] * inv));
    uint4* dst = reinterpret_cast<uint4*>(ah + (size_t)row * DM_ + lane * 16);
    dst[0] = o[0];
    dst[1] = o[1];
}

// ---------------- launch -----------------------------------------------------
extern "C" void kernel_launch(void* const* d_in, const int* in_sizes, int n_in,
                              void* d_out, int out_size) {
    const float* x   = (const float*)d_in[0];
    const float* mem = (const float*)d_in[1];
    const float* Wq  = (const float*)d_in[2];
    const float* bq  = (const float*)d_in[3];
    const float* Wm  = (const float*)d_in[4];
    const float* bm  = (const float*)d_in[5];
    float* out = (float*)d_out;

    __half *xh, *xl, *mh, *wqh, *wql, *wmh, *qh, *ql, *s16, *ah;
    float *tmx;
    cudaGetSymbolAddress((void**)&xh,  g_x_h);   cudaGetSymbolAddress((void**)&xl,  g_x_l);
    cudaGetSymbolAddress((void**)&mh,  g_mem_h);
    cudaGetSymbolAddress((void**)&wqh, g_wq_h);  cudaGetSymbolAddress((void**)&wql, g_wq_l);
    cudaGetSymbolAddress((void**)&wmh, g_wm_h);
    cudaGetSymbolAddress((void**)&qh,  g_q_h);   cudaGetSymbolAddress((void**)&ql,  g_q_l);
    cudaGetSymbolAddress((void**)&s16, g_s16);   cudaGetSymbolAddress((void**)&tmx, g_tmax);
    cudaGetSymbolAddress((void**)&ah,  g_att_h);

    constexpr int SM3 = 8 * 128 * 40 * 2;  // 81920 B (3-term)
    constexpr int SM1 = 4 * 128 * 40 * 2;  // 40960 B (1-term)
    cudaFuncSetAttribute(gemm_nt_c<true, 0, 3, false>,
                         cudaFuncAttributeMaxDynamicSharedMemorySize, SM3);
    cudaFuncSetAttribute(gemm_nt_c<false, 2, 1, true>,
                         cudaFuncAttributeMaxDynamicSharedMemorySize, SM1);
    cudaFuncSetAttribute(gemm_nt_c<true, 1, 1, false>,
                         cudaFuncAttributeMaxDynamicSharedMemorySize, SM1);

    // 0) fused prep: x copy + hi/lo split, mem hi-split, Wq hi/lo, Wm hi
    constexpr int PREP_BLOCKS =
        (BS_ * DQ_ / 4 + B_ * M_ * DM_ / 4 + DM_ * DQ_ / 4 + DQ_ * DM_ / 4) / 256;
    prep_kernel<<<PREP_BLOCKS, 256>>>(
        (const float4*)x, (float4*)out, (uint2*)xh, (uint2*)xl,
        (const float4*)mem, (uint2*)mh,
        (const float4*)Wq, (uint2*)wqh, (uint2*)wql,
        (const float4*)Wm, (uint2*)wmh);

    // 1) query = x @ Wq^T + bq  (3-term exact) -> hi/lo planes [8192, 512]
    gemm_nt_c<true, 0, 3, false><<<dim3(64, 4, 1), 256, SM3>>>(
        xh, xl, wqh, wql, qh, ql, bq, BS_, DM_, DQ_, 0, 0, 0, nullptr);

    // 2) scores(approx) = q_h @ mem_h^T (1-term fp16) + per-row tile maxes
    gemm_nt_c<false, 2, 1, true><<<dim3(16, 32, 4), 256, SM1>>>(
        qh, nullptr, mh, nullptr, s16, nullptr, nullptr, S_, M_, DM_,
        (size_t)S_ * DM_, (size_t)M_ * DM_, (size_t)S_ * M_, tmx);

    // 3) warp-per-row attend: single-pass online softmax + exact PV (2-way)
    attend_kernel<<<BS_ / 4, 128>>>(s16, tmx, qh, ql, mem, ah);

    // 4) transformed = attended_h @ Wm_h^T + bm (1-term) -> out tail
    gemm_nt_c<true, 1, 1, false><<<dim3(64, 8, 1), 256, SM1>>>(
        ah, nullptr, wmh, nullptr, out + (size_t)BS_ * DQ_, nullptr, bm,
        BS_, DQ_, DM_, 0, 0, 0, nullptr);
}